// round 3
// baseline (speedup 1.0000x reference)
#include <cuda_runtime.h>

// ----------------------------------------------------------------------------
// LSTM autoencoder, fp32, fused per-layer kernels.
// B=65536, T=8, D=60, H=128, L=64. PyTorch gate order i,f,g,o.
//
// Layer kernel: each CTA owns M=32 batch rows for all T=8 timesteps.
//   - gate matrix G[32][512] computed as X_t @ Wih^T + (bih+bhh) + H @ Whh^T
//   - 256 threads, each computes a 4-row x 16-col register tile (64 fp32 accums)
//   - weights staged to smem transposed in 16-k chunks (pitch 516, conflict-free)
//   - c-state in registers across timesteps, h-state in smem
//   - t==0 hidden GEMM skipped (h0 == 0)
// MODE 0: write h sequence to OutSeq [B,T,H]
// MODE 1: epilogue computes z = h_last @ W_lat^T + b_lat  -> OutAux [B,L]
// MODE 2: per-timestep projection out_t = h_t @ W_out^T + b_out -> OutAux [B,T,D]
// BCAST 1: input is [B,DIN], broadcast over time (decoder layer 0)
// ----------------------------------------------------------------------------

#define CB 65536
#define CT 8
#define CD 60
#define CH 128
#define CL 64
#define CG 512      // 4*H
#define MR 32       // batch rows per CTA
#define NT 256      // threads per CTA
#define KCHUNK 16   // k-chunk staged per sync
#define WTP 516     // Wt pitch (512 + 4) -> conflict-free lane reads

// scratch (device globals; no cudaMalloc allowed)
__device__ float g_h1[CB * CT * CH]; // 256 MB
__device__ float g_d1[CB * CT * CH]; // 256 MB
__device__ float g_z [CB * CL];      // 16 MB

__device__ __forceinline__ float sigf(float x)     { return 1.f / (1.f + __expf(-x)); }
__device__ __forceinline__ float tanhfast(float x) { return 2.f / (1.f + __expf(-2.f * x)) - 1.f; }

// inner GEMM over one staged 16-k chunk.
// arow points at act[(r0)*pitch + k0]; Wt holds Wt[kk][c] (pitch WTP).
__device__ __forceinline__ void gemm_chunk(const float* __restrict__ arow, int pitch,
                                           const float* __restrict__ Wt, int tx,
                                           float (&acc)[4][16], int klen)
{
    if (klen == KCHUNK) {
#pragma unroll 4
        for (int kk = 0; kk < KCHUNK; kk++) {
            float a0 = arow[kk];
            float a1 = arow[pitch + kk];
            float a2 = arow[2 * pitch + kk];
            float a3 = arow[3 * pitch + kk];
            const float* w = Wt + kk * WTP + tx;
#pragma unroll
            for (int j = 0; j < 16; j++) {
                float wv = w[32 * j];
                acc[0][j] = fmaf(a0, wv, acc[0][j]);
                acc[1][j] = fmaf(a1, wv, acc[1][j]);
                acc[2][j] = fmaf(a2, wv, acc[2][j]);
                acc[3][j] = fmaf(a3, wv, acc[3][j]);
            }
        }
    } else {
        for (int kk = 0; kk < klen; kk++) {
            float a0 = arow[kk];
            float a1 = arow[pitch + kk];
            float a2 = arow[2 * pitch + kk];
            float a3 = arow[3 * pitch + kk];
            const float* w = Wt + kk * WTP + tx;
#pragma unroll
            for (int j = 0; j < 16; j++) {
                float wv = w[32 * j];
                acc[0][j] = fmaf(a0, wv, acc[0][j]);
                acc[1][j] = fmaf(a1, wv, acc[1][j]);
                acc[2][j] = fmaf(a2, wv, acc[2][j]);
                acc[3][j] = fmaf(a3, wv, acc[3][j]);
            }
        }
    }
}

template <int DIN, int MODE, int BCAST>
__global__ __launch_bounds__(NT)
void lstm_kernel(const float* __restrict__ X,
                 const float* __restrict__ Wih, const float* __restrict__ Whh,
                 const float* __restrict__ bih, const float* __restrict__ bhh,
                 const float* __restrict__ Waux, const float* __restrict__ baux,
                 float* __restrict__ OutSeq, float* __restrict__ OutAux)
{
    extern __shared__ float sm[];
    float* Hbuf   = sm;                    // 32*128       = 4096
    float* Xbuf   = sm + 4096;             // 32*DIN(<=128)= 4096
    float* Wt     = sm + 8192;             // 16*516 / 64*132 = 8448
    float* bias_s = sm + 8192 + 8448;      // 512
    float* baux_s = bias_s + 512;          // 64
    float* Waux_s = baux_s + 64;           // 60*132 = 7920 (MODE==2 only)

    const int tid = threadIdx.x;
    const int tx  = tid & 31;
    const int ty  = tid >> 5;
    const int r0  = ty * 4;                       // this thread's first row
    const int rowbase = blockIdx.x * MR;          // global batch row base

    // init
    for (int i = tid; i < MR * CH; i += NT) Hbuf[i] = 0.f;
    for (int i = tid; i < CG; i += NT) bias_s[i] = bih[i] + bhh[i];
    if (MODE == 2) {
        for (int i = tid; i < CD * CH; i += NT) {
            int c = i >> 7, k = i & 127;
            Waux_s[c * 132 + k] = Waux[i];
        }
        for (int i = tid; i < CD; i += NT) baux_s[i] = baux[i];
    }
    if (BCAST) {
        for (int i = tid; i < MR * DIN; i += NT) {
            int r = i / DIN, k = i % DIN;
            Xbuf[i] = X[(size_t)(rowbase + r) * DIN + k];
        }
    }
    float cst[4][4];
#pragma unroll
    for (int r = 0; r < 4; r++)
#pragma unroll
        for (int q = 0; q < 4; q++) cst[r][q] = 0.f;
    __syncthreads();

    for (int t = 0; t < CT; ++t) {
        if (!BCAST) {
            // previous timestep ended with a __syncthreads(), Xbuf is free
            for (int i = tid; i < MR * DIN; i += NT) {
                int r = i / DIN, k = i % DIN;
                Xbuf[i] = X[((size_t)(rowbase + r) * CT + t) * DIN + k];
            }
        }

        float acc[4][16];
#pragma unroll
        for (int j = 0; j < 16; j++) {
            float b = bias_s[tx + 32 * j];
            acc[0][j] = b; acc[1][j] = b; acc[2][j] = b; acc[3][j] = b;
        }

        // ---- input GEMM: k over DIN, weights Wih [512][DIN] ----
        for (int k0 = 0; k0 < DIN; k0 += KCHUNK) {
            const int klen = (DIN - k0 < KCHUNK) ? (DIN - k0) : KCHUNK;
            __syncthreads(); // prior chunk consumed; Xbuf fill visible (1st iter)
            {
                int kt = tid & 15, cb = tid >> 4;
                if (kt < klen) {
#pragma unroll
                    for (int i = 0; i < 32; i++) {
                        int c = cb + 16 * i;
                        Wt[kt * WTP + c] = Wih[(size_t)c * DIN + k0 + kt];
                    }
                }
            }
            __syncthreads();
            gemm_chunk(Xbuf + r0 * DIN + k0, DIN, Wt, tx, acc, klen);
        }

        // ---- hidden GEMM: k over 128, weights Whh [512][128] (skip t==0, h==0) ----
        if (t > 0) {
            for (int k0 = 0; k0 < CH; k0 += KCHUNK) {
                __syncthreads();
                {
                    int kt = tid & 15, cb = tid >> 4;
#pragma unroll
                    for (int i = 0; i < 32; i++) {
                        int c = cb + 16 * i;
                        Wt[kt * WTP + c] = Whh[(size_t)c * CH + k0 + kt];
                    }
                }
                __syncthreads();
                gemm_chunk(Hbuf + r0 * CH + k0, CH, Wt, tx, acc, KCHUNK);
            }
        }
        __syncthreads(); // everyone done reading Hbuf/Xbuf for this timestep

        // ---- cell update; gate order i,f,g,o along the 512 dim ----
        // thread cell (r0+r, tx+32q): i=acc[r][q], f=acc[r][4+q], g=acc[r][8+q], o=acc[r][12+q]
#pragma unroll
        for (int r = 0; r < 4; r++) {
#pragma unroll
            for (int q = 0; q < 4; q++) {
                float ig = sigf(acc[r][q]);
                float fg = sigf(acc[r][4 + q]);
                float gg = tanhfast(acc[r][8 + q]);
                float og = sigf(acc[r][12 + q]);
                float cv = fmaf(fg, cst[r][q], ig * gg);
                cst[r][q] = cv;
                float hv = og * tanhfast(cv);
                Hbuf[(r0 + r) * CH + tx + 32 * q] = hv;
                if (MODE == 0) {
                    OutSeq[((size_t)(rowbase + r0 + r) * CT + t) * CH + tx + 32 * q] = hv;
                }
            }
        }

        if (MODE == 2) {
            __syncthreads(); // h_t complete in Hbuf
            // out_t[32][60] = h_t @ W_out^T + b_out
            for (int i = tid; i < MR * CD; i += NT) {
                int r = i / CD, c = i % CD;
                const float* hr = Hbuf + r * CH;
                const float* wr = Waux_s + c * 132;
                float s = baux_s[c];
#pragma unroll 8
                for (int k = 0; k < CH; k++) s = fmaf(hr[k], wr[k], s);
                OutAux[((size_t)(rowbase + r) * CT + t) * CD + c] = s;
            }
            // no sync needed: next t's chunk loop syncs before touching Wt/Xbuf,
            // and Hbuf is only re-written after that timestep's trailing sync.
        }
    }

    if (MODE == 1) {
        // z[32][64] = h_last @ W_lat^T + b_lat
        __syncthreads(); // h_last writes visible, Wt free
        for (int i = tid; i < CL * CH; i += NT) {
            int c = i >> 7, k = i & 127;
            Wt[c * 132 + k] = Waux[i]; // padded stage of W_lat [64][128]
        }
        __syncthreads();
        for (int i = tid; i < MR * CL; i += NT) {
            int r = i >> 6, c = i & 63;
            const float* hr = Hbuf + r * CH;
            const float* wr = Wt + c * 132;
            float s = baux[c];
#pragma unroll 8
            for (int k = 0; k < CH; k++) s = fmaf(hr[k], wr[k], s);
            OutAux[(size_t)(rowbase + r) * CL + c] = s;
        }
    }
}

// ----------------------------------------------------------------------------

extern "C" void kernel_launch(void* const* d_in, const int* in_sizes, int n_in,
                              void* d_out, int out_size)
{
    const float* x     = (const float*)d_in[0];
    const float* e0Wih = (const float*)d_in[1];
    const float* e0Whh = (const float*)d_in[2];
    const float* e0bih = (const float*)d_in[3];
    const float* e0bhh = (const float*)d_in[4];
    const float* e1Wih = (const float*)d_in[5];
    const float* e1Whh = (const float*)d_in[6];
    const float* e1bih = (const float*)d_in[7];
    const float* e1bhh = (const float*)d_in[8];
    const float* d0Wih = (const float*)d_in[9];
    const float* d0Whh = (const float*)d_in[10];
    const float* d0bih = (const float*)d_in[11];
    const float* d0bhh = (const float*)d_in[12];
    const float* d1Wih = (const float*)d_in[13];
    const float* d1Whh = (const float*)d_in[14];
    const float* d1bih = (const float*)d_in[15];
    const float* d1bhh = (const float*)d_in[16];
    const float* Wlat  = (const float*)d_in[17];
    const float* blat  = (const float*)d_in[18];
    const float* Wout  = (const float*)d_in[19];
    const float* bout  = (const float*)d_in[20];
    float* out = (float*)d_out;

    float *h1p, *d1p, *zp;
    cudaGetSymbolAddress((void**)&h1p, g_h1);
    cudaGetSymbolAddress((void**)&d1p, g_d1);
    cudaGetSymbolAddress((void**)&zp,  g_z);

    const int SM_STD = (4096 + 4096 + 8448 + 512 + 64) * 4;     // 68,864 B
    const int SM_PRJ = SM_STD + 7920 * 4;                       // 100,544 B

    cudaFuncSetAttribute((const void*)lstm_kernel<60, 0, 0>,
                         cudaFuncAttributeMaxDynamicSharedMemorySize, SM_STD);
    cudaFuncSetAttribute((const void*)lstm_kernel<128, 1, 0>,
                         cudaFuncAttributeMaxDynamicSharedMemorySize, SM_STD);
    cudaFuncSetAttribute((const void*)lstm_kernel<64, 0, 1>,
                         cudaFuncAttributeMaxDynamicSharedMemorySize, SM_STD);
    cudaFuncSetAttribute((const void*)lstm_kernel<128, 2, 0>,
                         cudaFuncAttributeMaxDynamicSharedMemorySize, SM_PRJ);

    dim3 grid(CB / MR); // 2048 CTAs

    // encoder layer 0: x [B,T,60] -> h1 seq [B,T,128]
    lstm_kernel<60, 0, 0><<<grid, NT, SM_STD>>>(
        x, e0Wih, e0Whh, e0bih, e0bhh, nullptr, nullptr, h1p, nullptr);
    // encoder layer 1: h1 -> h_last -> z = h_last @ W_lat^T + b_lat [B,64]
    lstm_kernel<128, 1, 0><<<grid, NT, SM_STD>>>(
        h1p, e1Wih, e1Whh, e1bih, e1bhh, Wlat, blat, nullptr, zp);
    // decoder layer 0: z broadcast over T -> d1 seq [B,T,128]
    lstm_kernel<64, 0, 1><<<grid, NT, SM_STD>>>(
        zp, d0Wih, d0Whh, d0bih, d0bhh, nullptr, nullptr, d1p, nullptr);
    // decoder layer 1 + output projection: d1 -> recon [B,T,60]
    lstm_kernel<128, 2, 0><<<grid, NT, SM_PRJ>>>(
        d1p, d1Wih, d1Whh, d1bih, d1bhh, Wout, bout, nullptr, out);
}

// round 4
// speedup vs baseline: 1.3709x; 1.3709x over previous
#include <cuda_runtime.h>

// ----------------------------------------------------------------------------
// LSTM autoencoder, fp32, fused per-layer kernels.
// B=65536, T=8, D=60, H=128, L=64. PyTorch gate order i,f,g,o.
//
// Layer kernel: each CTA owns M=32 batch rows for all T=8 timesteps.
//   - gate matrix G[32][512] computed as X_t @ Wih^T + (bih+bhh) + H @ Whh^T
//   - 256 threads, each computes a 4-row x 16-col register tile (64 fp32 accums)
//   - weights staged to smem transposed in 16-k chunks (pitch 516, conflict-free)
//   - c-state in registers across timesteps, h-state in smem
//   - t==0 hidden GEMM skipped (h0 == 0)
// MODE 0: write h sequence to OutSeq [B,T,H]
// MODE 1: epilogue computes z = h_last @ W_lat^T + b_lat  -> OutAux [B,L]
// MODE 2: per-timestep projection out_t = h_t @ W_out^T + b_out -> OutAux [B,T,D]
// BCAST 1: input is [B,DIN], broadcast over time (decoder layer 0)
// ----------------------------------------------------------------------------

#define CB 65536
#define CT 8
#define CD 60
#define CH 128
#define CL 64
#define CG 512      // 4*H
#define MR 32       // batch rows per CTA
#define NT 256      // threads per CTA
#define KCHUNK 16   // k-chunk staged per sync
#define WTP 516     // Wt pitch (512 + 4) -> conflict-free lane reads

// scratch (device globals; no cudaMalloc allowed)
__device__ float g_h1[CB * CT * CH]; // 256 MB
__device__ float g_d1[CB * CT * CH]; // 256 MB
__device__ float g_z [CB * CL];      // 16 MB

__device__ __forceinline__ float sigf(float x)     { return 1.f / (1.f + __expf(-x)); }
__device__ __forceinline__ float tanhfast(float x) { return 2.f / (1.f + __expf(-2.f * x)) - 1.f; }

// inner GEMM over one staged 16-k chunk.
// arow points at act[(r0)*pitch + k0]; Wt holds Wt[kk][c] (pitch WTP).
__device__ __forceinline__ void gemm_chunk(const float* __restrict__ arow, int pitch,
                                           const float* __restrict__ Wt, int tx,
                                           float (&acc)[4][16], int klen)
{
    if (klen == KCHUNK) {
#pragma unroll 4
        for (int kk = 0; kk < KCHUNK; kk++) {
            float a0 = arow[kk];
            float a1 = arow[pitch + kk];
            float a2 = arow[2 * pitch + kk];
            float a3 = arow[3 * pitch + kk];
            const float* w = Wt + kk * WTP + tx;
#pragma unroll
            for (int j = 0; j < 16; j++) {
                float wv = w[32 * j];
                acc[0][j] = fmaf(a0, wv, acc[0][j]);
                acc[1][j] = fmaf(a1, wv, acc[1][j]);
                acc[2][j] = fmaf(a2, wv, acc[2][j]);
                acc[3][j] = fmaf(a3, wv, acc[3][j]);
            }
        }
    } else {
        for (int kk = 0; kk < klen; kk++) {
            float a0 = arow[kk];
            float a1 = arow[pitch + kk];
            float a2 = arow[2 * pitch + kk];
            float a3 = arow[3 * pitch + kk];
            const float* w = Wt + kk * WTP + tx;
#pragma unroll
            for (int j = 0; j < 16; j++) {
                float wv = w[32 * j];
                acc[0][j] = fmaf(a0, wv, acc[0][j]);
                acc[1][j] = fmaf(a1, wv, acc[1][j]);
                acc[2][j] = fmaf(a2, wv, acc[2][j]);
                acc[3][j] = fmaf(a3, wv, acc[3][j]);
            }
        }
    }
}

template <int DIN, int MODE, int BCAST>
__global__ __launch_bounds__(NT)
void lstm_kernel(const float* __restrict__ X,
                 const float* __restrict__ Wih, const float* __restrict__ Whh,
                 const float* __restrict__ bih, const float* __restrict__ bhh,
                 const float* __restrict__ Waux, const float* __restrict__ baux,
                 float* __restrict__ OutSeq, float* __restrict__ OutAux)
{
    extern __shared__ float sm[];
    float* Hbuf   = sm;                    // 32*128       = 4096
    float* Xbuf   = sm + 4096;             // 32*DIN(<=128)= 4096
    float* Wt     = sm + 8192;             // 16*516 / 64*132 = 8448
    float* bias_s = sm + 8192 + 8448;      // 512
    float* baux_s = bias_s + 512;          // 64
    float* Waux_s = baux_s + 64;           // 60*132 = 7920 (MODE==2 only)

    const int tid = threadIdx.x;
    const int tx  = tid & 31;
    const int ty  = tid >> 5;
    const int r0  = ty * 4;                       // this thread's first row
    const int rowbase = blockIdx.x * MR;          // global batch row base

    // init
    for (int i = tid; i < MR * CH; i += NT) Hbuf[i] = 0.f;
    for (int i = tid; i < CG; i += NT) bias_s[i] = bih[i] + bhh[i];
    if (MODE == 2) {
        for (int i = tid; i < CD * CH; i += NT) {
            int c = i >> 7, k = i & 127;
            Waux_s[c * 132 + k] = Waux[i];
        }
        for (int i = tid; i < CD; i += NT) baux_s[i] = baux[i];
    }
    if (BCAST) {
        for (int i = tid; i < MR * DIN; i += NT) {
            int r = i / DIN, k = i % DIN;
            Xbuf[i] = X[(size_t)(rowbase + r) * DIN + k];
        }
    }
    float cst[4][4];
#pragma unroll
    for (int r = 0; r < 4; r++)
#pragma unroll
        for (int q = 0; q < 4; q++) cst[r][q] = 0.f;
    __syncthreads();

    for (int t = 0; t < CT; ++t) {
        if (!BCAST) {
            // previous timestep ended with a __syncthreads(), Xbuf is free
            for (int i = tid; i < MR * DIN; i += NT) {
                int r = i / DIN, k = i % DIN;
                Xbuf[i] = X[((size_t)(rowbase + r) * CT + t) * DIN + k];
            }
        }

        float acc[4][16];
#pragma unroll
        for (int j = 0; j < 16; j++) {
            float b = bias_s[tx + 32 * j];
            acc[0][j] = b; acc[1][j] = b; acc[2][j] = b; acc[3][j] = b;
        }

        // ---- input GEMM: k over DIN, weights Wih [512][DIN] ----
        for (int k0 = 0; k0 < DIN; k0 += KCHUNK) {
            const int klen = (DIN - k0 < KCHUNK) ? (DIN - k0) : KCHUNK;
            __syncthreads(); // prior chunk consumed; Xbuf fill visible (1st iter)
            {
                int kt = tid & 15, cb = tid >> 4;
                if (kt < klen) {
#pragma unroll
                    for (int i = 0; i < 32; i++) {
                        int c = cb + 16 * i;
                        Wt[kt * WTP + c] = Wih[(size_t)c * DIN + k0 + kt];
                    }
                }
            }
            __syncthreads();
            gemm_chunk(Xbuf + r0 * DIN + k0, DIN, Wt, tx, acc, klen);
        }

        // ---- hidden GEMM: k over 128, weights Whh [512][128] (skip t==0, h==0) ----
        if (t > 0) {
            for (int k0 = 0; k0 < CH; k0 += KCHUNK) {
                __syncthreads();
                {
                    int kt = tid & 15, cb = tid >> 4;
#pragma unroll
                    for (int i = 0; i < 32; i++) {
                        int c = cb + 16 * i;
                        Wt[kt * WTP + c] = Whh[(size_t)c * CH + k0 + kt];
                    }
                }
                __syncthreads();
                gemm_chunk(Hbuf + r0 * CH + k0, CH, Wt, tx, acc, KCHUNK);
            }
        }
        __syncthreads(); // everyone done reading Hbuf/Xbuf for this timestep

        // ---- cell update; gate order i,f,g,o along the 512 dim ----
        // thread cell (r0+r, tx+32q): i=acc[r][q], f=acc[r][4+q], g=acc[r][8+q], o=acc[r][12+q]
#pragma unroll
        for (int r = 0; r < 4; r++) {
#pragma unroll
            for (int q = 0; q < 4; q++) {
                float ig = sigf(acc[r][q]);
                float fg = sigf(acc[r][4 + q]);
                float gg = tanhfast(acc[r][8 + q]);
                float og = sigf(acc[r][12 + q]);
                float cv = fmaf(fg, cst[r][q], ig * gg);
                cst[r][q] = cv;
                float hv = og * tanhfast(cv);
                Hbuf[(r0 + r) * CH + tx + 32 * q] = hv;
                if (MODE == 0) {
                    OutSeq[((size_t)(rowbase + r0 + r) * CT + t) * CH + tx + 32 * q] = hv;
                }
            }
        }

        if (MODE == 2) {
            __syncthreads(); // h_t complete in Hbuf
            // out_t[32][60] = h_t @ W_out^T + b_out
            for (int i = tid; i < MR * CD; i += NT) {
                int r = i / CD, c = i % CD;
                const float* hr = Hbuf + r * CH;
                const float* wr = Waux_s + c * 132;
                float s = baux_s[c];
#pragma unroll 8
                for (int k = 0; k < CH; k++) s = fmaf(hr[k], wr[k], s);
                OutAux[((size_t)(rowbase + r) * CT + t) * CD + c] = s;
            }
            // no sync needed: next t's chunk loop syncs before touching Wt/Xbuf,
            // and Hbuf is only re-written after that timestep's trailing sync.
        }
    }

    if (MODE == 1) {
        // z[32][64] = h_last @ W_lat^T + b_lat
        __syncthreads(); // h_last writes visible, Wt free
        for (int i = tid; i < CL * CH; i += NT) {
            int c = i >> 7, k = i & 127;
            Wt[c * 132 + k] = Waux[i]; // padded stage of W_lat [64][128]
        }
        __syncthreads();
        for (int i = tid; i < MR * CL; i += NT) {
            int r = i >> 6, c = i & 63;
            const float* hr = Hbuf + r * CH;
            const float* wr = Wt + c * 132;
            float s = baux[c];
#pragma unroll 8
            for (int k = 0; k < CH; k++) s = fmaf(hr[k], wr[k], s);
            OutAux[(size_t)(rowbase + r) * CL + c] = s;
        }
    }
}

// ----------------------------------------------------------------------------

extern "C" void kernel_launch(void* const* d_in, const int* in_sizes, int n_in,
                              void* d_out, int out_size)
{
    const float* x     = (const float*)d_in[0];
    const float* e0Wih = (const float*)d_in[1];
    const float* e0Whh = (const float*)d_in[2];
    const float* e0bih = (const float*)d_in[3];
    const float* e0bhh = (const float*)d_in[4];
    const float* e1Wih = (const float*)d_in[5];
    const float* e1Whh = (const float*)d_in[6];
    const float* e1bih = (const float*)d_in[7];
    const float* e1bhh = (const float*)d_in[8];
    const float* d0Wih = (const float*)d_in[9];
    const float* d0Whh = (const float*)d_in[10];
    const float* d0bih = (const float*)d_in[11];
    const float* d0bhh = (const float*)d_in[12];
    const float* d1Wih = (const float*)d_in[13];
    const float* d1Whh = (const float*)d_in[14];
    const float* d1bih = (const float*)d_in[15];
    const float* d1bhh = (const float*)d_in[16];
    const float* Wlat  = (const float*)d_in[17];
    const float* blat  = (const float*)d_in[18];
    const float* Wout  = (const float*)d_in[19];
    const float* bout  = (const float*)d_in[20];
    float* out = (float*)d_out;

    float *h1p, *d1p, *zp;
    cudaGetSymbolAddress((void**)&h1p, g_h1);
    cudaGetSymbolAddress((void**)&d1p, g_d1);
    cudaGetSymbolAddress((void**)&zp,  g_z);

    const int SM_STD = (4096 + 4096 + 8448 + 512 + 64) * 4;     // 68,864 B
    const int SM_PRJ = SM_STD + 7920 * 4;                       // 100,544 B

    cudaFuncSetAttribute((const void*)lstm_kernel<60, 0, 0>,
                         cudaFuncAttributeMaxDynamicSharedMemorySize, SM_STD);
    cudaFuncSetAttribute((const void*)lstm_kernel<128, 1, 0>,
                         cudaFuncAttributeMaxDynamicSharedMemorySize, SM_STD);
    cudaFuncSetAttribute((const void*)lstm_kernel<64, 0, 1>,
                         cudaFuncAttributeMaxDynamicSharedMemorySize, SM_STD);
    cudaFuncSetAttribute((const void*)lstm_kernel<128, 2, 0>,
                         cudaFuncAttributeMaxDynamicSharedMemorySize, SM_PRJ);

    dim3 grid(CB / MR); // 2048 CTAs

    // encoder layer 0: x [B,T,60] -> h1 seq [B,T,128]
    lstm_kernel<60, 0, 0><<<grid, NT, SM_STD>>>(
        x, e0Wih, e0Whh, e0bih, e0bhh, nullptr, nullptr, h1p, nullptr);
    // encoder layer 1: h1 -> h_last -> z = h_last @ W_lat^T + b_lat [B,64]
    lstm_kernel<128, 1, 0><<<grid, NT, SM_STD>>>(
        h1p, e1Wih, e1Whh, e1bih, e1bhh, Wlat, blat, nullptr, zp);
    // decoder layer 0: z broadcast over T -> d1 seq [B,T,128]
    lstm_kernel<64, 0, 1><<<grid, NT, SM_STD>>>(
        zp, d0Wih, d0Whh, d0bih, d0bhh, nullptr, nullptr, d1p, nullptr);
    // decoder layer 1 + output projection: d1 -> recon [B,T,60]
    lstm_kernel<128, 2, 0><<<grid, NT, SM_PRJ>>>(
        d1p, d1Wih, d1Whh, d1bih, d1bhh, Wout, bout, nullptr, out);
}

// round 5
// speedup vs baseline: 1.3713x; 1.0003x over previous
#include <cuda_runtime.h>

// ----------------------------------------------------------------------------
// LSTM autoencoder, fp32, fused per-layer kernels.
// B=65536, T=8, D=60, H=128, L=64. PyTorch gate order i,f,g,o.
//
// Layer kernel: each CTA owns M=32 batch rows for all T=8 timesteps.
//   - gate matrix G[32][512] computed as X_t @ Wih^T + (bih+bhh) + H @ Whh^T
//   - 256 threads, each computes a 4-row x 16-col register tile (64 fp32 accums)
//   - weights staged to smem transposed in 16-k chunks (pitch 516, conflict-free)
//   - c-state in registers across timesteps, h-state in smem
//   - t==0 hidden GEMM skipped (h0 == 0)
// MODE 0: write h sequence to OutSeq [B,T,H]
// MODE 1: epilogue computes z = h_last @ W_lat^T + b_lat  -> OutAux [B,L]
// MODE 2: per-timestep projection out_t = h_t @ W_out^T + b_out -> OutAux [B,T,D]
// BCAST 1: input is [B,DIN], broadcast over time (decoder layer 0)
// ----------------------------------------------------------------------------

#define CB 65536
#define CT 8
#define CD 60
#define CH 128
#define CL 64
#define CG 512      // 4*H
#define MR 32       // batch rows per CTA
#define NT 256      // threads per CTA
#define KCHUNK 16   // k-chunk staged per sync
#define WTP 516     // Wt pitch (512 + 4) -> conflict-free lane reads

// scratch (device globals; no cudaMalloc allowed)
__device__ float g_h1[CB * CT * CH]; // 256 MB
__device__ float g_d1[CB * CT * CH]; // 256 MB
__device__ float g_z [CB * CL];      // 16 MB

__device__ __forceinline__ float sigf(float x)     { return 1.f / (1.f + __expf(-x)); }
__device__ __forceinline__ float tanhfast(float x) { return 2.f / (1.f + __expf(-2.f * x)) - 1.f; }

// inner GEMM over one staged 16-k chunk.
// arow points at act[(r0)*pitch + k0]; Wt holds Wt[kk][c] (pitch WTP).
__device__ __forceinline__ void gemm_chunk(const float* __restrict__ arow, int pitch,
                                           const float* __restrict__ Wt, int tx,
                                           float (&acc)[4][16], int klen)
{
    if (klen == KCHUNK) {
#pragma unroll 4
        for (int kk = 0; kk < KCHUNK; kk++) {
            float a0 = arow[kk];
            float a1 = arow[pitch + kk];
            float a2 = arow[2 * pitch + kk];
            float a3 = arow[3 * pitch + kk];
            const float* w = Wt + kk * WTP + tx;
#pragma unroll
            for (int j = 0; j < 16; j++) {
                float wv = w[32 * j];
                acc[0][j] = fmaf(a0, wv, acc[0][j]);
                acc[1][j] = fmaf(a1, wv, acc[1][j]);
                acc[2][j] = fmaf(a2, wv, acc[2][j]);
                acc[3][j] = fmaf(a3, wv, acc[3][j]);
            }
        }
    } else {
        for (int kk = 0; kk < klen; kk++) {
            float a0 = arow[kk];
            float a1 = arow[pitch + kk];
            float a2 = arow[2 * pitch + kk];
            float a3 = arow[3 * pitch + kk];
            const float* w = Wt + kk * WTP + tx;
#pragma unroll
            for (int j = 0; j < 16; j++) {
                float wv = w[32 * j];
                acc[0][j] = fmaf(a0, wv, acc[0][j]);
                acc[1][j] = fmaf(a1, wv, acc[1][j]);
                acc[2][j] = fmaf(a2, wv, acc[2][j]);
                acc[3][j] = fmaf(a3, wv, acc[3][j]);
            }
        }
    }
}

template <int DIN, int MODE, int BCAST>
__global__ __launch_bounds__(NT)
void lstm_kernel(const float* __restrict__ X,
                 const float* __restrict__ Wih, const float* __restrict__ Whh,
                 const float* __restrict__ bih, const float* __restrict__ bhh,
                 const float* __restrict__ Waux, const float* __restrict__ baux,
                 float* __restrict__ OutSeq, float* __restrict__ OutAux)
{
    extern __shared__ float sm[];
    float* Hbuf   = sm;                    // 32*128       = 4096
    float* Xbuf   = sm + 4096;             // 32*DIN(<=128)= 4096
    float* Wt     = sm + 8192;             // 16*516 / 64*132 = 8448
    float* bias_s = sm + 8192 + 8448;      // 512
    float* baux_s = bias_s + 512;          // 64
    float* Waux_s = baux_s + 64;           // 60*132 = 7920 (MODE==2 only)

    const int tid = threadIdx.x;
    const int tx  = tid & 31;
    const int ty  = tid >> 5;
    const int r0  = ty * 4;                       // this thread's first row
    const int rowbase = blockIdx.x * MR;          // global batch row base

    // init
    for (int i = tid; i < MR * CH; i += NT) Hbuf[i] = 0.f;
    for (int i = tid; i < CG; i += NT) bias_s[i] = bih[i] + bhh[i];
    if (MODE == 2) {
        for (int i = tid; i < CD * CH; i += NT) {
            int c = i >> 7, k = i & 127;
            Waux_s[c * 132 + k] = Waux[i];
        }
        for (int i = tid; i < CD; i += NT) baux_s[i] = baux[i];
    }
    if (BCAST) {
        for (int i = tid; i < MR * DIN; i += NT) {
            int r = i / DIN, k = i % DIN;
            Xbuf[i] = X[(size_t)(rowbase + r) * DIN + k];
        }
    }
    float cst[4][4];
#pragma unroll
    for (int r = 0; r < 4; r++)
#pragma unroll
        for (int q = 0; q < 4; q++) cst[r][q] = 0.f;
    __syncthreads();

    for (int t = 0; t < CT; ++t) {
        if (!BCAST) {
            // previous timestep ended with a __syncthreads(), Xbuf is free
            for (int i = tid; i < MR * DIN; i += NT) {
                int r = i / DIN, k = i % DIN;
                Xbuf[i] = X[((size_t)(rowbase + r) * CT + t) * DIN + k];
            }
        }

        float acc[4][16];
#pragma unroll
        for (int j = 0; j < 16; j++) {
            float b = bias_s[tx + 32 * j];
            acc[0][j] = b; acc[1][j] = b; acc[2][j] = b; acc[3][j] = b;
        }

        // ---- input GEMM: k over DIN, weights Wih [512][DIN] ----
        for (int k0 = 0; k0 < DIN; k0 += KCHUNK) {
            const int klen = (DIN - k0 < KCHUNK) ? (DIN - k0) : KCHUNK;
            __syncthreads(); // prior chunk consumed; Xbuf fill visible (1st iter)
            {
                int kt = tid & 15, cb = tid >> 4;
                if (kt < klen) {
#pragma unroll
                    for (int i = 0; i < 32; i++) {
                        int c = cb + 16 * i;
                        Wt[kt * WTP + c] = Wih[(size_t)c * DIN + k0 + kt];
                    }
                }
            }
            __syncthreads();
            gemm_chunk(Xbuf + r0 * DIN + k0, DIN, Wt, tx, acc, klen);
        }

        // ---- hidden GEMM: k over 128, weights Whh [512][128] (skip t==0, h==0) ----
        if (t > 0) {
            for (int k0 = 0; k0 < CH; k0 += KCHUNK) {
                __syncthreads();
                {
                    int kt = tid & 15, cb = tid >> 4;
#pragma unroll
                    for (int i = 0; i < 32; i++) {
                        int c = cb + 16 * i;
                        Wt[kt * WTP + c] = Whh[(size_t)c * CH + k0 + kt];
                    }
                }
                __syncthreads();
                gemm_chunk(Hbuf + r0 * CH + k0, CH, Wt, tx, acc, KCHUNK);
            }
        }
        __syncthreads(); // everyone done reading Hbuf/Xbuf for this timestep

        // ---- cell update; gate order i,f,g,o along the 512 dim ----
        // thread cell (r0+r, tx+32q): i=acc[r][q], f=acc[r][4+q], g=acc[r][8+q], o=acc[r][12+q]
#pragma unroll
        for (int r = 0; r < 4; r++) {
#pragma unroll
            for (int q = 0; q < 4; q++) {
                float ig = sigf(acc[r][q]);
                float fg = sigf(acc[r][4 + q]);
                float gg = tanhfast(acc[r][8 + q]);
                float og = sigf(acc[r][12 + q]);
                float cv = fmaf(fg, cst[r][q], ig * gg);
                cst[r][q] = cv;
                float hv = og * tanhfast(cv);
                Hbuf[(r0 + r) * CH + tx + 32 * q] = hv;
                if (MODE == 0) {
                    OutSeq[((size_t)(rowbase + r0 + r) * CT + t) * CH + tx + 32 * q] = hv;
                }
            }
        }

        if (MODE == 2) {
            __syncthreads(); // h_t complete in Hbuf
            // out_t[32][60] = h_t @ W_out^T + b_out
            for (int i = tid; i < MR * CD; i += NT) {
                int r = i / CD, c = i % CD;
                const float* hr = Hbuf + r * CH;
                const float* wr = Waux_s + c * 132;
                float s = baux_s[c];
#pragma unroll 8
                for (int k = 0; k < CH; k++) s = fmaf(hr[k], wr[k], s);
                OutAux[((size_t)(rowbase + r) * CT + t) * CD + c] = s;
            }
            // no sync needed: next t's chunk loop syncs before touching Wt/Xbuf,
            // and Hbuf is only re-written after that timestep's trailing sync.
        }
    }

    if (MODE == 1) {
        // z[32][64] = h_last @ W_lat^T + b_lat
        __syncthreads(); // h_last writes visible, Wt free
        for (int i = tid; i < CL * CH; i += NT) {
            int c = i >> 7, k = i & 127;
            Wt[c * 132 + k] = Waux[i]; // padded stage of W_lat [64][128]
        }
        __syncthreads();
        for (int i = tid; i < MR * CL; i += NT) {
            int r = i >> 6, c = i & 63;
            const float* hr = Hbuf + r * CH;
            const float* wr = Wt + c * 132;
            float s = baux[c];
#pragma unroll 8
            for (int k = 0; k < CH; k++) s = fmaf(hr[k], wr[k], s);
            OutAux[(size_t)(rowbase + r) * CL + c] = s;
        }
    }
}

// ----------------------------------------------------------------------------

extern "C" void kernel_launch(void* const* d_in, const int* in_sizes, int n_in,
                              void* d_out, int out_size)
{
    const float* x     = (const float*)d_in[0];
    const float* e0Wih = (const float*)d_in[1];
    const float* e0Whh = (const float*)d_in[2];
    const float* e0bih = (const float*)d_in[3];
    const float* e0bhh = (const float*)d_in[4];
    const float* e1Wih = (const float*)d_in[5];
    const float* e1Whh = (const float*)d_in[6];
    const float* e1bih = (const float*)d_in[7];
    const float* e1bhh = (const float*)d_in[8];
    const float* d0Wih = (const float*)d_in[9];
    const float* d0Whh = (const float*)d_in[10];
    const float* d0bih = (const float*)d_in[11];
    const float* d0bhh = (const float*)d_in[12];
    const float* d1Wih = (const float*)d_in[13];
    const float* d1Whh = (const float*)d_in[14];
    const float* d1bih = (const float*)d_in[15];
    const float* d1bhh = (const float*)d_in[16];
    const float* Wlat  = (const float*)d_in[17];
    const float* blat  = (const float*)d_in[18];
    const float* Wout  = (const float*)d_in[19];
    const float* bout  = (const float*)d_in[20];
    float* out = (float*)d_out;

    float *h1p, *d1p, *zp;
    cudaGetSymbolAddress((void**)&h1p, g_h1);
    cudaGetSymbolAddress((void**)&d1p, g_d1);
    cudaGetSymbolAddress((void**)&zp,  g_z);

    const int SM_STD = (4096 + 4096 + 8448 + 512 + 64) * 4;     // 68,864 B
    const int SM_PRJ = SM_STD + 7920 * 4;                       // 100,544 B

    cudaFuncSetAttribute((const void*)lstm_kernel<60, 0, 0>,
                         cudaFuncAttributeMaxDynamicSharedMemorySize, SM_STD);
    cudaFuncSetAttribute((const void*)lstm_kernel<128, 1, 0>,
                         cudaFuncAttributeMaxDynamicSharedMemorySize, SM_STD);
    cudaFuncSetAttribute((const void*)lstm_kernel<64, 0, 1>,
                         cudaFuncAttributeMaxDynamicSharedMemorySize, SM_STD);
    cudaFuncSetAttribute((const void*)lstm_kernel<128, 2, 0>,
                         cudaFuncAttributeMaxDynamicSharedMemorySize, SM_PRJ);

    dim3 grid(CB / MR); // 2048 CTAs

    // encoder layer 0: x [B,T,60] -> h1 seq [B,T,128]
    lstm_kernel<60, 0, 0><<<grid, NT, SM_STD>>>(
        x, e0Wih, e0Whh, e0bih, e0bhh, nullptr, nullptr, h1p, nullptr);
    // encoder layer 1: h1 -> h_last -> z = h_last @ W_lat^T + b_lat [B,64]
    lstm_kernel<128, 1, 0><<<grid, NT, SM_STD>>>(
        h1p, e1Wih, e1Whh, e1bih, e1bhh, Wlat, blat, nullptr, zp);
    // decoder layer 0: z broadcast over T -> d1 seq [B,T,128]
    lstm_kernel<64, 0, 1><<<grid, NT, SM_STD>>>(
        zp, d0Wih, d0Whh, d0bih, d0bhh, nullptr, nullptr, d1p, nullptr);
    // decoder layer 1 + output projection: d1 -> recon [B,T,60]
    lstm_kernel<128, 2, 0><<<grid, NT, SM_PRJ>>>(
        d1p, d1Wih, d1Whh, d1bih, d1bhh, Wout, bout, nullptr, out);
}